// round 14
// baseline (speedup 1.0000x reference)
#include <cuda_runtime.h>

#define NPTS 16384
#define KNB  16

#define GRID  32
#define NCELL (GRID * GRID * GRID)
#define GLO   (-5.0f)
#define GH    0.3125f
#define GINVH 3.2f

typedef unsigned long long u64;

// Scratch (no allocations allowed).
__device__ __align__(16) float g_A[NPTS * 128];
__device__ int g_nbr[NPTS * KNB];
__device__ __align__(16) float4 g_pos4[NPTS];
__device__ int g_pcell[NPTS];
__device__ int g_prank[NPTS];
__device__ int g_cellcnt[NCELL];
__device__ int g_cellstart[NCELL + 1];
__device__ __align__(16) float4 g_spts[NPTS];
__device__ int g_sidx[NPTS];

// ---------------------------------------------------------------------------
// Packed f32x2 helpers (edge kernel phase 3).
// ---------------------------------------------------------------------------
__device__ __forceinline__ u64 fdup(float x) {
    u64 r; asm("mov.b64 %0, {%1, %1};" : "=l"(r) : "f"(x)); return r;
}
__device__ __forceinline__ void fma2(u64& d, u64 a, u64 b) {
    asm("fma.rn.f32x2 %0, %1, %2, %0;" : "+l"(d) : "l"(a), "l"(b));
}
__device__ __forceinline__ float2 u2f(u64 v) {
    float2 r; asm("mov.b64 {%0, %1}, %2;" : "=f"(r.x), "=f"(r.y) : "l"(v)); return r;
}

// ---------------------------------------------------------------------------
// Grid build (3 launches): zero -> count(+rank) -> fused scan+scatter.
// ---------------------------------------------------------------------------
__device__ __forceinline__ int cell_coord(float v) {
    int c = (int)floorf((v - GLO) * GINVH);
    return min(max(c, 0), GRID - 1);
}

__global__ void zero_cells_kernel() {
    const int i = blockIdx.x * 1024 + threadIdx.x;
    if (i < NCELL) g_cellcnt[i] = 0;
}

__global__ void count_kernel(const float* __restrict__ pos) {
    const int i = blockIdx.x * blockDim.x + threadIdx.x;
    const float x = pos[3 * i], y = pos[3 * i + 1], z = pos[3 * i + 2];
    g_pos4[i] = make_float4(x, y, z, x * x + y * y + z * z);
    const int c = (cell_coord(x) * GRID + cell_coord(y)) * GRID + cell_coord(z);
    g_pcell[i] = c;
    g_prank[i] = atomicAdd(&g_cellcnt[c], 1);
}

__global__ void __launch_bounds__(1024) scan_scatter_kernel() {
    __shared__ int part[1024];
    const int t = threadIdx.x;
    const int base = t * (NCELL / 1024);
    int s = 0;
#pragma unroll
    for (int k = 0; k < NCELL / 1024; ++k) s += g_cellcnt[base + k];
    part[t] = s;
    __syncthreads();
    for (int off = 1; off < 1024; off <<= 1) {
        const int v = (t >= off) ? part[t - off] : 0;
        __syncthreads();
        part[t] += v;
        __syncthreads();
    }
    int run = (t == 0) ? 0 : part[t - 1];
#pragma unroll
    for (int k = 0; k < NCELL / 1024; ++k) {
        const int c = base + k;
        g_cellstart[c] = run;
        run += g_cellcnt[c];
    }
    if (t == 1023) g_cellstart[NCELL] = run;
    __syncthreads();
    for (int i = t; i < NPTS; i += 1024) {
        const int slot = g_cellstart[g_pcell[i]] + g_prank[i];
        g_spts[slot] = g_pos4[i];
        g_sidx[slot] = i;
    }
}

// ---------------------------------------------------------------------------
// Warp-cooperative bitonic helpers on packed u64 keys.
// ---------------------------------------------------------------------------
__device__ __forceinline__ u64 sort32(u64 v, int lane) {
#pragma unroll
    for (int k = 2; k <= 32; k <<= 1) {
#pragma unroll
        for (int j = k >> 1; j > 0; j >>= 1) {
            const u64 o = __shfl_xor_sync(0xffffffffu, v, j);
            const bool keepMin = (((lane & j) == 0) == ((lane & k) == 0));
            v = ((v < o) == keepMin) ? v : o;
        }
    }
    return v;
}

__device__ __forceinline__ u64 merge_lower(u64 a, u64 b, int lane) {
    const u64 br = __shfl_sync(0xffffffffu, b, 31 - lane);
    u64 m = (a < br) ? a : br;
#pragma unroll
    for (int j = 16; j > 0; j >>= 1) {
        const u64 o = __shfl_xor_sync(0xffffffffu, m, j);
        const bool keepMin = ((lane & j) == 0);
        m = ((m < o) == keepMin) ? m : o;
    }
    return m;
}

__device__ __forceinline__ void flush_merge(u64& v, float& kthf,
                                            const u64* buf, int cnt, int lane) {
    __syncwarp();
    u64 b0 = (lane < cnt) ? buf[lane] : ~0ull;
    b0 = sort32(b0, lane);
    if (cnt > 32) {
        u64 b1 = (32 + lane < cnt) ? buf[32 + lane] : ~0ull;
        b1 = sort32(b1, lane);
        b0 = merge_lower(b0, b1, lane);
    }
    v = merge_lower(v, b0, lane);
    const unsigned m = (unsigned)(__shfl_sync(0xffffffffu, v, 15) >> 32);
    kthf = (m & 0x80000000u) ? __uint_as_float(m & 0x7fffffffu)
                             : __uint_as_float(~m);
}

// ---------------------------------------------------------------------------
// Grid KNN v3. Fast path: 3x3x3 clipped neighborhood; lane-parallel range
// loads; candidate INDEX LIST materialized in smem once (kills the 9-run
// decode ALU tax), then a lean 32-wide stream loop. Same candidate set /
// keys / break condition as R13 => bit-identical neighbors. Fallbacks:
// decode path (list overflow) and ring expansion from r=2 (rare).
// ---------------------------------------------------------------------------
#define SENTINEL 0xFF7FFFFFFFFFFFFFull   // decodes to +FLT_MAX
#define LCAP 1152

__global__ void __launch_bounds__(256) knn_grid_kernel() {
    __shared__ int s_idx[8][LCAP];
    __shared__ u64 s_buf[8][64];
    const int lane = threadIdx.x & 31;
    const int w    = threadIdx.x >> 5;
    const int row  = blockIdx.x * 8 + w;
    const unsigned lmask = (1u << lane) - 1u;
    const float4 p = g_pos4[row];
    const int cx = cell_coord(p.x);
    const int cy = cell_coord(p.y);
    const int cz = cell_coord(p.z);

    u64 v = SENTINEL;
    float kthf = 3.402823466e38f;
    int cnt = 0;

    // ---- fast path: 3x3x3 clipped neighborhood (== rings 0 and 1) ----
    {
        const int x0 = max(cx - 1, 0), x1 = min(cx + 1, GRID - 1);
        const int y0 = max(cy - 1, 0), y1 = min(cy + 1, GRID - 1);
        const int z0 = max(cz - 1, 0), z1 = min(cz + 1, GRID - 1);
        const int ny = y1 - y0 + 1;
        const int ncols = (x1 - x0 + 1) * ny;

        int rs = 0, rlen = 0;
        if (lane < ncols) {
            const int x = x0 + lane / ny;
            const int y = y0 + lane % ny;
            const int cb = (x * GRID + y) * GRID;
            rs   = g_cellstart[cb + z0];
            rlen = g_cellstart[cb + z1 + 1] - rs;
        }
        // exclusive prefix of run lengths across lanes
        int incl = rlen;
#pragma unroll
        for (int o = 1; o < 32; o <<= 1) {
            const int tv = __shfl_up_sync(0xffffffffu, incl, o);
            if (lane >= o) incl += tv;
        }
        const int pre   = incl - rlen;
        const int total = __shfl_sync(0xffffffffu, incl, 31);
        int s9[9], p9[9], l9[9];
#pragma unroll
        for (int m = 0; m < 9; ++m) {
            s9[m] = __shfl_sync(0xffffffffu, rs, m);
            p9[m] = __shfl_sync(0xffffffffu, pre, m);
            l9[m] = __shfl_sync(0xffffffffu, rlen, m);
        }

        if (total <= LCAP) {
            // materialize candidate index list (one pass, cheap STS)
#pragma unroll 1
            for (int m = 0; m < 9; ++m) {
                const int lm = l9[m], pm = p9[m], sm = s9[m];
                for (int i0 = lane; i0 < lm; i0 += 32)
                    s_idx[w][pm + i0] = sm + i0;
            }
            __syncwarp();
            // lean stream loop
            for (int i0 = 0; i0 < total; i0 += 32) {
                const int idx = i0 + lane;
                const bool in = idx < total;
                const int jj = in ? s_idx[w][idx] : 0;
                const float4 c4 = in ? g_spts[jj] : make_float4(0.f, 0.f, 0.f, 3.4e38f);
                const float dot = fmaf(p.x, c4.x, fmaf(p.y, c4.y, p.z * c4.z));
                const float d2  = fmaf(-2.f, dot, p.w + c4.w);
                const bool pred = in && (d2 <= kthf);
                const unsigned bal = __ballot_sync(0xffffffffu, pred);
                if (bal) {
                    if (pred) {
                        unsigned u = __float_as_uint(d2);
                        u = (u & 0x80000000u) ? ~u : (u | 0x80000000u);
                        s_buf[w][cnt + __popc(bal & lmask)] =
                            ((u64)u << 32) | (unsigned)g_sidx[jj];
                    }
                    cnt += __popc(bal);
                    if (cnt > 32) { flush_merge(v, kthf, s_buf[w], cnt, lane); cnt = 0; }
                }
            }
        } else {
            // overflow fallback: R13-exact 9-run decode path
            for (int i0 = 0; i0 < total; i0 += 32) {
                const int idx = i0 + lane;
                const bool in = idx < total;
                int jj = 0;
#pragma unroll
                for (int m = 0; m < 9; ++m) {
                    const bool c = (idx >= p9[m]) && (idx < p9[m] + l9[m]);
                    jj = c ? (s9[m] + idx - p9[m]) : jj;
                }
                const float4 c4 = in ? g_spts[jj] : make_float4(0.f, 0.f, 0.f, 3.4e38f);
                const float dot = fmaf(p.x, c4.x, fmaf(p.y, c4.y, p.z * c4.z));
                const float d2  = fmaf(-2.f, dot, p.w + c4.w);
                const bool pred = in && (d2 <= kthf);
                const unsigned bal = __ballot_sync(0xffffffffu, pred);
                if (bal) {
                    if (pred) {
                        unsigned u = __float_as_uint(d2);
                        u = (u & 0x80000000u) ? ~u : (u | 0x80000000u);
                        s_buf[w][cnt + __popc(bal & lmask)] =
                            ((u64)u << 32) | (unsigned)g_sidx[jj];
                    }
                    cnt += __popc(bal);
                    if (cnt > 32) { flush_merge(v, kthf, s_buf[w], cnt, lane); cnt = 0; }
                }
            }
        }
        if (cnt) { flush_merge(v, kthf, s_buf[w], cnt, lane); cnt = 0; }
    }

    // ---- fallback: ring expansion from r=2 (rare) ----
    if (kthf > GH * GH) {
        for (int r = 2; r <= GRID; ++r) {
            const float R = (float)(r - 1) * GH;
            if (kthf <= R * R) break;
            for (int dx = -r; dx <= r; ++dx) {
                const int x = cx + dx;
                if (x < 0 || x >= GRID) continue;
                for (int dy = -r; dy <= r; ++dy) {
                    const int y = cy + dy;
                    if (y < 0 || y >= GRID) continue;
                    const bool face = (dx == -r || dx == r || dy == -r || dy == r);
                    const int nrun = face ? 1 : 2;
#pragma unroll 1
                    for (int rr = 0; rr < nrun; ++rr) {
                        int zlo, zhi;
                        if (face)         { zlo = cz - r; zhi = cz + r; }
                        else if (rr == 0) { zlo = cz - r; zhi = cz - r; }
                        else              { zlo = cz + r; zhi = cz + r; }
                        zlo = max(zlo, 0); zhi = min(zhi, GRID - 1);
                        if (zlo > zhi) continue;
                        const int cbase = (x * GRID + y) * GRID;
                        const int s  = g_cellstart[cbase + zlo];
                        const int e2 = g_cellstart[cbase + zhi + 1];
                        for (int j = s; j < e2; j += 32) {
                            const int jj = j + lane;
                            const bool in = jj < e2;
                            const float4 c4 = in ? g_spts[jj]
                                                 : make_float4(0.f, 0.f, 0.f, 3.4e38f);
                            const float dot = fmaf(p.x, c4.x, fmaf(p.y, c4.y, p.z * c4.z));
                            const float d2  = fmaf(-2.f, dot, p.w + c4.w);
                            const bool pred = in && (d2 <= kthf);
                            const unsigned bal = __ballot_sync(0xffffffffu, pred);
                            if (bal) {
                                if (pred) {
                                    unsigned u = __float_as_uint(d2);
                                    u = (u & 0x80000000u) ? ~u : (u | 0x80000000u);
                                    s_buf[w][cnt + __popc(bal & lmask)] =
                                        ((u64)u << 32) | (unsigned)g_sidx[jj];
                                }
                                cnt += __popc(bal);
                                if (cnt > 32) {
                                    flush_merge(v, kthf, s_buf[w], cnt, lane);
                                    cnt = 0;
                                }
                            }
                        }
                    }
                }
            }
            if (cnt) { flush_merge(v, kthf, s_buf[w], cnt, lane); cnt = 0; }
        }
    }
    if (cnt) flush_merge(v, kthf, s_buf[w], cnt, lane);
    if (lane < KNB) g_nbr[row * KNB + lane] = (int)(v & 0xFFFFFFFFull);
}

// ---------------------------------------------------------------------------
// Node projection (R6-exact).
// ---------------------------------------------------------------------------
template <int CIN, int C, bool FIRST>
__global__ void __launch_bounds__(128) proj_kernel(const float* __restrict__ x,
                                                   const float* __restrict__ pos,
                                                   const float* __restrict__ nrm,
                                                   const float* __restrict__ Wa,
                                                   const float* __restrict__ ba) {
    constexpr int TPN = C / 4;
    __shared__ __align__(16) float sW[CIN * C];
    __shared__ __align__(16) float sb[C];
    const int t = threadIdx.x;
    for (int i = t; i < CIN * C; i += 128) sW[i] = Wa[i];
    for (int i = t; i < C; i += 128) sb[i] = ba[i];
    __syncthreads();

    const int n  = blockIdx.x * (128 / TPN) + t / TPN;
    const int c0 = (t % TPN) * 4;
    float4 acc = *reinterpret_cast<const float4*>(&sb[c0]);
#pragma unroll
    for (int k = 0; k < CIN; ++k) {
        float xv;
        if (FIRST) xv = (k < 3) ? pos[n * 3 + k] : nrm[n * 3 + (k - 3)];
        else       xv = x[n * CIN + k];
        const float4 wv = *reinterpret_cast<const float4*>(&sW[k * C + c0]);
        acc.x = fmaf(xv, wv.x, acc.x);
        acc.y = fmaf(xv, wv.y, acc.y);
        acc.z = fmaf(xv, wv.z, acc.z);
        acc.w = fmaf(xv, wv.w, acc.w);
    }
    *reinterpret_cast<float4*>(&g_A[n * C + c0]) = acc;
}

// ---------------------------------------------------------------------------
// Fused edge kernel (R6-exact 623us version: FFMA2 4x4 phase 3).
// ---------------------------------------------------------------------------
template <int C, int G, int NPB>
__global__ void __launch_bounds__(2 * C) edge_kernel(
    const float* __restrict__ pos,
    const float* __restrict__ Wa, int cin_node,
    const float* __restrict__ gmm, const float* __restrict__ bta,
    const float* __restrict__ Wb,  const float* __restrict__ bb,
    float* __restrict__ out) {
    constexpr int B  = 2 * C;
    constexpr int HS = 20;
    constexpr int NG = 4;
    extern __shared__ float smem[];
    float* s_Wb   = smem;
    float* s_H    = s_Wb + C * C;
    float* s_Wrel = s_H + NG * C * HS;
    float* s_g    = s_Wrel + 3 * C;
    float* s_b    = s_g + C;
    float* s_bb   = s_b + C;

    const int t = threadIdx.x;
    for (int i = t; i < C * C; i += B) s_Wb[i] = Wb[i];
    for (int i = t; i < 3 * C; i += B) s_Wrel[i] = Wa[cin_node * C + i];
    for (int i = t; i < C; i += B) { s_g[i] = gmm[i]; s_b[i] = bta[i]; s_bb[i] = bb[i]; }
    __syncthreads();

    const int e    = t & 15;
    const int g    = t >> 4;
    const int lane = t & 31;
    const int w    = t >> 5;
    const int et   = lane & 3;
    const int fi   = lane >> 2;
    const int q3   = (C == 128) ? (w >> 1) : w;
    const int f0   = ((C == 128) ? (w & 1) * 64 : 0) + fi * 8;

    for (int s0 = 0; s0 < NPB; s0 += NG) {
#pragma unroll
        for (int q = 0; q < NG; ++q) {
            const int i = blockIdx.x * NPB + s0 + q;
            float* Hq = s_H + q * C * HS;
            const int j = g_nbr[i * KNB + e];
            const float rx = pos[j * 3 + 0] - pos[i * 3 + 0];
            const float ry = pos[j * 3 + 1] - pos[i * 3 + 1];
            const float rz = pos[j * 3 + 2] - pos[i * 3 + 2];
            const int c0 = g * 8;
            const float* Ar = g_A + j * C + c0;
            const float4 a0 = *reinterpret_cast<const float4*>(Ar);
            const float4 a1 = *reinterpret_cast<const float4*>(Ar + 4);
            float h[8] = {a0.x, a0.y, a0.z, a0.w, a1.x, a1.y, a1.z, a1.w};
            float sum = 0.f;
#pragma unroll
            for (int cc = 0; cc < 8; ++cc) {
                const int c = c0 + cc;
                h[cc] = h[cc] + rx * s_Wrel[c] + ry * s_Wrel[C + c] + rz * s_Wrel[2 * C + c];
                sum += h[cc];
            }
            const float mean = sum * 0.125f;
            float vs = 0.f;
#pragma unroll
            for (int cc = 0; cc < 8; ++cc) { const float d = h[cc] - mean; vs = fmaf(d, d, vs); }
            const float inv = rsqrtf(fmaf(vs, 0.125f, 1e-5f));
#pragma unroll
            for (int cc = 0; cc < 8; ++cc) {
                const int c = c0 + cc;
                const float vv = fmaf((h[cc] - mean) * inv, s_g[c], s_b[c]);
                Hq[c * HS + e] = fmaxf(vv, 0.f);
            }
        }
        __syncthreads();
        {
            const int i = blockIdx.x * NPB + s0 + q3;
            const float* Hq = s_H + q3 * C * HS;
            u64 acc2[4][4];
#pragma unroll
            for (int a = 0; a < 4; ++a)
#pragma unroll
                for (int fp = 0; fp < 4; ++fp) acc2[a][fp] = 0ull;

#pragma unroll 4
            for (int c = 0; c < C; ++c) {
                const float4 h4 = *reinterpret_cast<const float4*>(&Hq[c * HS + et * 4]);
                const ulonglong2 wA = *reinterpret_cast<const ulonglong2*>(&s_Wb[c * C + f0]);
                const ulonglong2 wC = *reinterpret_cast<const ulonglong2*>(&s_Wb[c * C + f0 + 4]);
                const u64 wv[4] = {wA.x, wA.y, wC.x, wC.y};
                const u64 hh[4] = {fdup(h4.x), fdup(h4.y), fdup(h4.z), fdup(h4.w)};
#pragma unroll
                for (int a = 0; a < 4; ++a)
#pragma unroll
                    for (int fp = 0; fp < 4; ++fp)
                        fma2(acc2[a][fp], hh[a], wv[fp]);
            }
            float m[8];
#pragma unroll
            for (int fp = 0; fp < 4; ++fp) {
                const float2 v0 = u2f(acc2[0][fp]);
                const float2 v1 = u2f(acc2[1][fp]);
                const float2 v2 = u2f(acc2[2][fp]);
                const float2 v3 = u2f(acc2[3][fp]);
                m[2 * fp]     = fmaxf(fmaxf(v0.x, v1.x), fmaxf(v2.x, v3.x));
                m[2 * fp + 1] = fmaxf(fmaxf(v0.y, v1.y), fmaxf(v2.y, v3.y));
            }
#pragma unroll
            for (int f = 0; f < 8; ++f) {
                m[f] = fmaxf(m[f], __shfl_xor_sync(0xffffffffu, m[f], 1));
                m[f] = fmaxf(m[f], __shfl_xor_sync(0xffffffffu, m[f], 2));
            }
            if (et == 0) {
                float4 r0, r1;
                r0.x = fmaxf(m[0] + s_bb[f0 + 0], 0.f);
                r0.y = fmaxf(m[1] + s_bb[f0 + 1], 0.f);
                r0.z = fmaxf(m[2] + s_bb[f0 + 2], 0.f);
                r0.w = fmaxf(m[3] + s_bb[f0 + 3], 0.f);
                r1.x = fmaxf(m[4] + s_bb[f0 + 4], 0.f);
                r1.y = fmaxf(m[5] + s_bb[f0 + 5], 0.f);
                r1.z = fmaxf(m[6] + s_bb[f0 + 6], 0.f);
                r1.w = fmaxf(m[7] + s_bb[f0 + 7], 0.f);
                *reinterpret_cast<float4*>(&out[i * C + f0])     = r0;
                *reinterpret_cast<float4*>(&out[i * C + f0 + 4]) = r1;
            }
        }
        __syncthreads();
    }
}

// ---------------------------------------------------------------------------
extern "C" void kernel_launch(void* const* d_in, const int* in_sizes, int n_in,
                              void* d_out, int out_size) {
    const float* pos    = (const float*)d_in[0];
    const float* normal = (const float*)d_in[1];
    const float* W1a = (const float*)d_in[2];
    const float* b1a = (const float*)d_in[3];
    const float* g1  = (const float*)d_in[4];
    const float* be1 = (const float*)d_in[5];
    const float* W1b = (const float*)d_in[6];
    const float* b1b = (const float*)d_in[7];
    const float* W2a = (const float*)d_in[8];
    const float* b2a = (const float*)d_in[9];
    const float* g2  = (const float*)d_in[10];
    const float* be2 = (const float*)d_in[11];
    const float* W2b = (const float*)d_in[12];
    const float* b2b = (const float*)d_in[13];
    const float* W3a = (const float*)d_in[14];
    const float* b3a = (const float*)d_in[15];
    const float* g3  = (const float*)d_in[16];
    const float* be3 = (const float*)d_in[17];
    const float* W3b = (const float*)d_in[18];
    const float* b3b = (const float*)d_in[19];

    float* out = (float*)d_out;
    float* h1 = out;
    float* h2 = out + NPTS * 64;
    float* h3 = out + NPTS * 128;

    const int SMEM64  = (64 * 64  + 4 * 64 * 20  + 3 * 64  + 3 * 64)  * 4;
    const int SMEM128 = (128 * 128 + 4 * 128 * 20 + 3 * 128 + 3 * 128) * 4;
    cudaFuncSetAttribute((const void*)edge_kernel<64, 8, 8>,
                         cudaFuncAttributeMaxDynamicSharedMemorySize, SMEM64);
    cudaFuncSetAttribute((const void*)edge_kernel<128, 16, 8>,
                         cudaFuncAttributeMaxDynamicSharedMemorySize, SMEM128);

    zero_cells_kernel<<<NCELL / 1024, 1024>>>();   // launch 0
    count_kernel<<<NPTS / 256, 256>>>(pos);        // launch 1
    scan_scatter_kernel<<<1, 1024>>>();            // launch 2
    knn_grid_kernel<<<NPTS / 8, 256>>>();          // launch 3 <- profiled

    proj_kernel<6, 64, true><<<NPTS / 8, 128>>>(nullptr, pos, normal, W1a, b1a);
    edge_kernel<64, 8, 8><<<NPTS / 8, 128, SMEM64>>>(pos, W1a, 6, g1, be1, W1b, b1b, h1);

    proj_kernel<64, 64, false><<<NPTS / 8, 128>>>(h1, nullptr, nullptr, W2a, b2a);
    edge_kernel<64, 8, 8><<<NPTS / 8, 128, SMEM64>>>(pos, W2a, 64, g2, be2, W2b, b2b, h2);

    proj_kernel<64, 128, false><<<NPTS / 4, 128>>>(h2, nullptr, nullptr, W3a, b3a);
    edge_kernel<128, 16, 8><<<NPTS / 8, 256, SMEM128>>>(pos, W3a, 64, g3, be3, W3b, b3b, h3);
}

// round 16
// speedup vs baseline: 1.1361x; 1.1361x over previous
#include <cuda_runtime.h>

#define NPTS 16384
#define KNB  16

typedef unsigned long long u64;

// Scratch (no allocations allowed).
__device__ __align__(16) float g_A[NPTS * 128];
__device__ int g_nbr[NPTS * KNB];
__device__ __align__(16) float4 g_pos4[NPTS];

// ---------------------------------------------------------------------------
// Packed f32x2 helpers.
// ---------------------------------------------------------------------------
__device__ __forceinline__ u64 fdup(float x) {
    u64 r; asm("mov.b64 %0, {%1, %1};" : "=l"(r) : "f"(x)); return r;
}
__device__ __forceinline__ void fma2(u64& d, u64 a, u64 b) {
    asm("fma.rn.f32x2 %0, %1, %2, %0;" : "+l"(d) : "l"(a), "l"(b));
}
__device__ __forceinline__ float2 u2f(u64 v) {
    float2 r; asm("mov.b64 {%0, %1}, %2;" : "=f"(r.x), "=f"(r.y) : "l"(v)); return r;
}

// ---------------------------------------------------------------------------
// Pack pos -> float4 (x,y,z,|p|^2) once.
// ---------------------------------------------------------------------------
__global__ void pos4_kernel(const float* __restrict__ pos) {
    const int i = blockIdx.x * blockDim.x + threadIdx.x;
    const float x = pos[3 * i], y = pos[3 * i + 1], z = pos[3 * i + 2];
    g_pos4[i] = make_float4(x, y, z, x * x + y * y + z * z);
}

// ---------------------------------------------------------------------------
// Warp-cooperative bitonic helpers + brute KNN (R6-exact, best known).
// ---------------------------------------------------------------------------
__device__ __forceinline__ u64 sort32(u64 v, int lane) {
#pragma unroll
    for (int k = 2; k <= 32; k <<= 1) {
#pragma unroll
        for (int j = k >> 1; j > 0; j >>= 1) {
            const u64 o = __shfl_xor_sync(0xffffffffu, v, j);
            const bool keepMin = (((lane & j) == 0) == ((lane & k) == 0));
            v = ((v < o) == keepMin) ? v : o;
        }
    }
    return v;
}
__device__ __forceinline__ u64 merge_lower(u64 a, u64 b, int lane) {
    const u64 br = __shfl_sync(0xffffffffu, b, 31 - lane);
    u64 m = (a < br) ? a : br;
#pragma unroll
    for (int j = 16; j > 0; j >>= 1) {
        const u64 o = __shfl_xor_sync(0xffffffffu, m, j);
        const bool keepMin = ((lane & j) == 0);
        m = ((m < o) == keepMin) ? m : o;
    }
    return m;
}
__device__ __forceinline__ void flush_merge(u64& v, u64& kth,
                                            const u64* buf, int cnt, int lane) {
    __syncwarp();
    u64 b0 = (lane < cnt) ? buf[lane] : ~0ull;
    b0 = sort32(b0, lane);
    if (cnt > 32) {
        u64 b1 = (32 + lane < cnt) ? buf[32 + lane] : ~0ull;
        b1 = sort32(b1, lane);
        b0 = merge_lower(b0, b1, lane);
    }
    v = merge_lower(v, b0, lane);
    kth = __shfl_sync(0xffffffffu, v, 15);
}

#define WPB  16
#define TILE 1024

__global__ void __launch_bounds__(32 * WPB) knn_kernel() {
    __shared__ float4 s_cand[TILE];
    __shared__ u64 s_buf[WPB][64];

    const int lane = threadIdx.x & 31;
    const int w    = threadIdx.x >> 5;
    const int row  = blockIdx.x * WPB + w;
    const float4 p = g_pos4[row];

    u64 v   = ~0ull;
    u64 kth = ~0ull;
    int bufcnt = 0;

    for (int base = 0; base < NPTS; base += TILE) {
        __syncthreads();
        for (int i = threadIdx.x; i < TILE; i += 32 * WPB) s_cand[i] = g_pos4[base + i];
        __syncthreads();
#pragma unroll 4
        for (int i = 0; i < TILE; i += 32) {
            const float4 c = s_cand[i + lane];
            const float dot = fmaf(p.x, c.x, fmaf(p.y, c.y, p.z * c.z));
            const float d2  = fmaf(-2.f, dot, p.w + c.w);
            unsigned u = __float_as_uint(d2);
            u = (u & 0x80000000u) ? ~u : (u | 0x80000000u);
            const u64 key = ((u64)u << 32) | (unsigned)(base + i + lane);
            const bool pred = key < kth;
            const unsigned bal = __ballot_sync(0xffffffffu, pred);
            if (bal) {
                if (pred)
                    s_buf[w][bufcnt + __popc(bal & ((1u << lane) - 1u))] = key;
                bufcnt += __popc(bal);
                if (bufcnt > 32) {
                    flush_merge(v, kth, s_buf[w], bufcnt, lane);
                    bufcnt = 0;
                }
            }
        }
    }
    if (bufcnt) flush_merge(v, kth, s_buf[w], bufcnt, lane);
    if (lane < KNB) g_nbr[row * KNB + lane] = (int)(v & 0xFFFFFFFFull);
}

// ---------------------------------------------------------------------------
// Node projection (R6-exact).
// ---------------------------------------------------------------------------
template <int CIN, int C, bool FIRST>
__global__ void __launch_bounds__(128) proj_kernel(const float* __restrict__ x,
                                                   const float* __restrict__ pos,
                                                   const float* __restrict__ nrm,
                                                   const float* __restrict__ Wa,
                                                   const float* __restrict__ ba) {
    constexpr int TPN = C / 4;
    __shared__ __align__(16) float sW[CIN * C];
    __shared__ __align__(16) float sb[C];
    const int t = threadIdx.x;
    for (int i = t; i < CIN * C; i += 128) sW[i] = Wa[i];
    for (int i = t; i < C; i += 128) sb[i] = ba[i];
    __syncthreads();

    const int n  = blockIdx.x * (128 / TPN) + t / TPN;
    const int c0 = (t % TPN) * 4;
    float4 acc = *reinterpret_cast<const float4*>(&sb[c0]);
#pragma unroll
    for (int k = 0; k < CIN; ++k) {
        float xv;
        if (FIRST) xv = (k < 3) ? pos[n * 3 + k] : nrm[n * 3 + (k - 3)];
        else       xv = x[n * CIN + k];
        const float4 wv = *reinterpret_cast<const float4*>(&sW[k * C + c0]);
        acc.x = fmaf(xv, wv.x, acc.x);
        acc.y = fmaf(xv, wv.y, acc.y);
        acc.z = fmaf(xv, wv.z, acc.z);
        acc.w = fmaf(xv, wv.w, acc.w);
    }
    *reinterpret_cast<float4*>(&g_A[n * C + c0]) = acc;
}

// ---------------------------------------------------------------------------
// edge64 kernel (conv1/conv2). R16: NG=2 (smem 28.2KB -> 7 blocks/SM),
// __launch_bounds__(128, 7). Phase-3 retiled to 2 warps/node x 32 channels;
// per-channel accumulation order over c and the fmax/shfl reduction are
// IDENTICAL to the R6 version -> bitwise-same outputs.
// ---------------------------------------------------------------------------
__global__ void __launch_bounds__(128, 7) edge64_kernel(
    const float* __restrict__ Wa, int cin_node,
    const float* __restrict__ gmm, const float* __restrict__ bta,
    const float* __restrict__ Wb,  const float* __restrict__ bb,
    float* __restrict__ out) {
    constexpr int C  = 64;
    constexpr int HS = 20;
    constexpr int NG = 2;
    constexpr int NPB = 8;
    __shared__ __align__(16) float s_Wb[C * C];
    __shared__ __align__(16) float s_H[NG * C * HS];
    __shared__ __align__(16) float s_Wrel[3 * C];
    __shared__ float s_g[C], s_b[C], s_bb[C];

    const int t = threadIdx.x;
    for (int i = t; i < C * C; i += 128) s_Wb[i] = Wb[i];
    for (int i = t; i < 3 * C; i += 128) s_Wrel[i] = Wa[cin_node * C + i];
    for (int i = t; i < C; i += 128) { s_g[i] = gmm[i]; s_b[i] = bta[i]; s_bb[i] = bb[i]; }
    __syncthreads();

    const int e    = t & 15;
    const int g    = t >> 4;
    const int lane = t & 31;
    const int w    = t >> 5;
    const int et   = lane & 3;
    const int fi   = lane >> 2;
    const int q3   = w >> 1;                 // node within batch (2 warps/node)
    const int ch0  = (w & 1) * 32 + fi * 4;  // 4 output channels per lane

    for (int s0 = 0; s0 < NPB; s0 += NG) {
        // ---- phase 1 + 2 ----
#pragma unroll
        for (int q = 0; q < NG; ++q) {
            const int i = blockIdx.x * NPB + s0 + q;
            float* Hq = s_H + q * C * HS;
            const int j = g_nbr[i * KNB + e];
            const float4 pj = g_pos4[j];
            const float4 pi = g_pos4[i];
            const float rx = pj.x - pi.x;
            const float ry = pj.y - pi.y;
            const float rz = pj.z - pi.z;
            const int c0 = g * 8;
            const float* Ar = g_A + j * C + c0;
            const float4 a0 = *reinterpret_cast<const float4*>(Ar);
            const float4 a1 = *reinterpret_cast<const float4*>(Ar + 4);
            float h[8] = {a0.x, a0.y, a0.z, a0.w, a1.x, a1.y, a1.z, a1.w};
            float sum = 0.f;
#pragma unroll
            for (int cc = 0; cc < 8; ++cc) {
                const int c = c0 + cc;
                h[cc] = h[cc] + rx * s_Wrel[c] + ry * s_Wrel[C + c] + rz * s_Wrel[2 * C + c];
                sum += h[cc];
            }
            const float mean = sum * 0.125f;
            float vs = 0.f;
#pragma unroll
            for (int cc = 0; cc < 8; ++cc) { const float d = h[cc] - mean; vs = fmaf(d, d, vs); }
            const float inv = rsqrtf(fmaf(vs, 0.125f, 1e-5f));
#pragma unroll
            for (int cc = 0; cc < 8; ++cc) {
                const int c = c0 + cc;
                const float vv = fmaf((h[cc] - mean) * inv, s_g[c], s_b[c]);
                Hq[c * HS + e] = fmaxf(vv, 0.f);
            }
        }
        __syncthreads();
        // ---- phase 3: 2 warps/node, 4 edges x 4 channels per lane (FFMA2) ----
        {
            const int i = blockIdx.x * NPB + s0 + q3;
            const float* Hq = s_H + q3 * C * HS;
            u64 acc2[4][2];
#pragma unroll
            for (int a = 0; a < 4; ++a) { acc2[a][0] = 0ull; acc2[a][1] = 0ull; }

#pragma unroll 4
            for (int c = 0; c < C; ++c) {
                const float4 h4 = *reinterpret_cast<const float4*>(&Hq[c * HS + et * 4]);
                const ulonglong2 wv = *reinterpret_cast<const ulonglong2*>(&s_Wb[c * C + ch0]);
                const u64 hh[4] = {fdup(h4.x), fdup(h4.y), fdup(h4.z), fdup(h4.w)};
#pragma unroll
                for (int a = 0; a < 4; ++a) {
                    fma2(acc2[a][0], hh[a], wv.x);
                    fma2(acc2[a][1], hh[a], wv.y);
                }
            }
            float m[4];
#pragma unroll
            for (int p = 0; p < 2; ++p) {
                const float2 v0 = u2f(acc2[0][p]);
                const float2 v1 = u2f(acc2[1][p]);
                const float2 v2 = u2f(acc2[2][p]);
                const float2 v3 = u2f(acc2[3][p]);
                m[2 * p]     = fmaxf(fmaxf(v0.x, v1.x), fmaxf(v2.x, v3.x));
                m[2 * p + 1] = fmaxf(fmaxf(v0.y, v1.y), fmaxf(v2.y, v3.y));
            }
#pragma unroll
            for (int f = 0; f < 4; ++f) {
                m[f] = fmaxf(m[f], __shfl_xor_sync(0xffffffffu, m[f], 1));
                m[f] = fmaxf(m[f], __shfl_xor_sync(0xffffffffu, m[f], 2));
            }
            if (et == 0) {
                float4 r;
                r.x = fmaxf(m[0] + s_bb[ch0 + 0], 0.f);
                r.y = fmaxf(m[1] + s_bb[ch0 + 1], 0.f);
                r.z = fmaxf(m[2] + s_bb[ch0 + 2], 0.f);
                r.w = fmaxf(m[3] + s_bb[ch0 + 3], 0.f);
                *reinterpret_cast<float4*>(&out[i * C + ch0]) = r;
            }
        }
        __syncthreads();
    }
}

// ---------------------------------------------------------------------------
// Fused edge kernel C=128 (R6-exact: FFMA2 4x4 phase 3).
// ---------------------------------------------------------------------------
template <int C, int G, int NPB>
__global__ void __launch_bounds__(2 * C) edge_kernel(
    const float* __restrict__ pos,
    const float* __restrict__ Wa, int cin_node,
    const float* __restrict__ gmm, const float* __restrict__ bta,
    const float* __restrict__ Wb,  const float* __restrict__ bb,
    float* __restrict__ out) {
    constexpr int B  = 2 * C;
    constexpr int HS = 20;
    constexpr int NG = 4;
    extern __shared__ float smem[];
    float* s_Wb   = smem;
    float* s_H    = s_Wb + C * C;
    float* s_Wrel = s_H + NG * C * HS;
    float* s_g    = s_Wrel + 3 * C;
    float* s_b    = s_g + C;
    float* s_bb   = s_b + C;

    const int t = threadIdx.x;
    for (int i = t; i < C * C; i += B) s_Wb[i] = Wb[i];
    for (int i = t; i < 3 * C; i += B) s_Wrel[i] = Wa[cin_node * C + i];
    for (int i = t; i < C; i += B) { s_g[i] = gmm[i]; s_b[i] = bta[i]; s_bb[i] = bb[i]; }
    __syncthreads();

    const int e    = t & 15;
    const int g    = t >> 4;
    const int lane = t & 31;
    const int w    = t >> 5;
    const int et   = lane & 3;
    const int fi   = lane >> 2;
    const int q3   = w >> 1;
    const int f0   = (w & 1) * 64 + fi * 8;

    for (int s0 = 0; s0 < NPB; s0 += NG) {
#pragma unroll
        for (int q = 0; q < NG; ++q) {
            const int i = blockIdx.x * NPB + s0 + q;
            float* Hq = s_H + q * C * HS;
            const int j = g_nbr[i * KNB + e];
            const float rx = pos[j * 3 + 0] - pos[i * 3 + 0];
            const float ry = pos[j * 3 + 1] - pos[i * 3 + 1];
            const float rz = pos[j * 3 + 2] - pos[i * 3 + 2];
            const int c0 = g * 8;
            const float* Ar = g_A + j * C + c0;
            const float4 a0 = *reinterpret_cast<const float4*>(Ar);
            const float4 a1 = *reinterpret_cast<const float4*>(Ar + 4);
            float h[8] = {a0.x, a0.y, a0.z, a0.w, a1.x, a1.y, a1.z, a1.w};
            float sum = 0.f;
#pragma unroll
            for (int cc = 0; cc < 8; ++cc) {
                const int c = c0 + cc;
                h[cc] = h[cc] + rx * s_Wrel[c] + ry * s_Wrel[C + c] + rz * s_Wrel[2 * C + c];
                sum += h[cc];
            }
            const float mean = sum * 0.125f;
            float vs = 0.f;
#pragma unroll
            for (int cc = 0; cc < 8; ++cc) { const float d = h[cc] - mean; vs = fmaf(d, d, vs); }
            const float inv = rsqrtf(fmaf(vs, 0.125f, 1e-5f));
#pragma unroll
            for (int cc = 0; cc < 8; ++cc) {
                const int c = c0 + cc;
                const float vv = fmaf((h[cc] - mean) * inv, s_g[c], s_b[c]);
                Hq[c * HS + e] = fmaxf(vv, 0.f);
            }
        }
        __syncthreads();
        {
            const int i = blockIdx.x * NPB + s0 + q3;
            const float* Hq = s_H + q3 * C * HS;
            u64 acc2[4][4];
#pragma unroll
            for (int a = 0; a < 4; ++a)
#pragma unroll
                for (int fp = 0; fp < 4; ++fp) acc2[a][fp] = 0ull;

#pragma unroll 4
            for (int c = 0; c < C; ++c) {
                const float4 h4 = *reinterpret_cast<const float4*>(&Hq[c * HS + et * 4]);
                const ulonglong2 wA = *reinterpret_cast<const ulonglong2*>(&s_Wb[c * C + f0]);
                const ulonglong2 wC = *reinterpret_cast<const ulonglong2*>(&s_Wb[c * C + f0 + 4]);
                const u64 wv[4] = {wA.x, wA.y, wC.x, wC.y};
                const u64 hh[4] = {fdup(h4.x), fdup(h4.y), fdup(h4.z), fdup(h4.w)};
#pragma unroll
                for (int a = 0; a < 4; ++a)
#pragma unroll
                    for (int fp = 0; fp < 4; ++fp)
                        fma2(acc2[a][fp], hh[a], wv[fp]);
            }
            float m[8];
#pragma unroll
            for (int fp = 0; fp < 4; ++fp) {
                const float2 v0 = u2f(acc2[0][fp]);
                const float2 v1 = u2f(acc2[1][fp]);
                const float2 v2 = u2f(acc2[2][fp]);
                const float2 v3 = u2f(acc2[3][fp]);
                m[2 * fp]     = fmaxf(fmaxf(v0.x, v1.x), fmaxf(v2.x, v3.x));
                m[2 * fp + 1] = fmaxf(fmaxf(v0.y, v1.y), fmaxf(v2.y, v3.y));
            }
#pragma unroll
            for (int f = 0; f < 8; ++f) {
                m[f] = fmaxf(m[f], __shfl_xor_sync(0xffffffffu, m[f], 1));
                m[f] = fmaxf(m[f], __shfl_xor_sync(0xffffffffu, m[f], 2));
            }
            if (et == 0) {
                float4 r0, r1;
                r0.x = fmaxf(m[0] + s_bb[f0 + 0], 0.f);
                r0.y = fmaxf(m[1] + s_bb[f0 + 1], 0.f);
                r0.z = fmaxf(m[2] + s_bb[f0 + 2], 0.f);
                r0.w = fmaxf(m[3] + s_bb[f0 + 3], 0.f);
                r1.x = fmaxf(m[4] + s_bb[f0 + 4], 0.f);
                r1.y = fmaxf(m[5] + s_bb[f0 + 5], 0.f);
                r1.z = fmaxf(m[6] + s_bb[f0 + 6], 0.f);
                r1.w = fmaxf(m[7] + s_bb[f0 + 7], 0.f);
                *reinterpret_cast<float4*>(&out[i * C + f0])     = r0;
                *reinterpret_cast<float4*>(&out[i * C + f0 + 4]) = r1;
            }
        }
        __syncthreads();
    }
}

// ---------------------------------------------------------------------------
extern "C" void kernel_launch(void* const* d_in, const int* in_sizes, int n_in,
                              void* d_out, int out_size) {
    const float* pos    = (const float*)d_in[0];
    const float* normal = (const float*)d_in[1];
    const float* W1a = (const float*)d_in[2];
    const float* b1a = (const float*)d_in[3];
    const float* g1  = (const float*)d_in[4];
    const float* be1 = (const float*)d_in[5];
    const float* W1b = (const float*)d_in[6];
    const float* b1b = (const float*)d_in[7];
    const float* W2a = (const float*)d_in[8];
    const float* b2a = (const float*)d_in[9];
    const float* g2  = (const float*)d_in[10];
    const float* be2 = (const float*)d_in[11];
    const float* W2b = (const float*)d_in[12];
    const float* b2b = (const float*)d_in[13];
    const float* W3a = (const float*)d_in[14];
    const float* b3a = (const float*)d_in[15];
    const float* g3  = (const float*)d_in[16];
    const float* be3 = (const float*)d_in[17];
    const float* W3b = (const float*)d_in[18];
    const float* b3b = (const float*)d_in[19];

    float* out = (float*)d_out;
    float* h1 = out;
    float* h2 = out + NPTS * 64;
    float* h3 = out + NPTS * 128;

    const int SMEM128 = (128 * 128 + 4 * 128 * 20 + 3 * 128 + 3 * 128) * 4;
    cudaFuncSetAttribute((const void*)edge_kernel<128, 16, 8>,
                         cudaFuncAttributeMaxDynamicSharedMemorySize, SMEM128);

    pos4_kernel<<<NPTS / 256, 256>>>(pos);
    knn_kernel<<<NPTS / WPB, 32 * WPB>>>();

    proj_kernel<6, 64, true><<<NPTS / 8, 128>>>(nullptr, pos, normal, W1a, b1a);
    edge64_kernel<<<NPTS / 8, 128>>>(W1a, 6, g1, be1, W1b, b1b, h1);

    proj_kernel<64, 64, false><<<NPTS / 8, 128>>>(h1, nullptr, nullptr, W2a, b2a);
    edge64_kernel<<<NPTS / 8, 128>>>(W2a, 64, g2, be2, W2b, b2b, h2);

    proj_kernel<64, 128, false><<<NPTS / 4, 128>>>(h2, nullptr, nullptr, W3a, b3a);
    edge_kernel<128, 16, 8><<<NPTS / 8, 256, SMEM128>>>(pos, W3a, 64, g3, be3, W3b, b3b, h3);
}

// round 17
// speedup vs baseline: 1.1817x; 1.0401x over previous
#include <cuda_runtime.h>

#define NPTS 16384
#define KNB  16

typedef unsigned long long u64;

// Scratch (no allocations allowed).
__device__ __align__(16) float g_A[NPTS * 128];
__device__ int g_nbr[NPTS * KNB];
__device__ __align__(16) float4 g_pos4[NPTS];

// ---------------------------------------------------------------------------
// Packed f32x2 helpers.
// ---------------------------------------------------------------------------
__device__ __forceinline__ u64 fdup(float x) {
    u64 r; asm("mov.b64 %0, {%1, %1};" : "=l"(r) : "f"(x)); return r;
}
__device__ __forceinline__ void fma2(u64& d, u64 a, u64 b) {
    asm("fma.rn.f32x2 %0, %1, %2, %0;" : "+l"(d) : "l"(a), "l"(b));
}
__device__ __forceinline__ float2 u2f(u64 v) {
    float2 r; asm("mov.b64 {%0, %1}, %2;" : "=f"(r.x), "=f"(r.y) : "l"(v)); return r;
}

// ---------------------------------------------------------------------------
// Pack pos -> float4 (x,y,z,|p|^2) once.
// ---------------------------------------------------------------------------
__global__ void pos4_kernel(const float* __restrict__ pos) {
    const int i = blockIdx.x * blockDim.x + threadIdx.x;
    const float x = pos[3 * i], y = pos[3 * i + 1], z = pos[3 * i + 2];
    g_pos4[i] = make_float4(x, y, z, x * x + y * y + z * z);
}

// ---------------------------------------------------------------------------
// Warp-cooperative bitonic helpers + brute KNN (R6-exact, best known).
// ---------------------------------------------------------------------------
__device__ __forceinline__ u64 sort32(u64 v, int lane) {
#pragma unroll
    for (int k = 2; k <= 32; k <<= 1) {
#pragma unroll
        for (int j = k >> 1; j > 0; j >>= 1) {
            const u64 o = __shfl_xor_sync(0xffffffffu, v, j);
            const bool keepMin = (((lane & j) == 0) == ((lane & k) == 0));
            v = ((v < o) == keepMin) ? v : o;
        }
    }
    return v;
}
__device__ __forceinline__ u64 merge_lower(u64 a, u64 b, int lane) {
    const u64 br = __shfl_sync(0xffffffffu, b, 31 - lane);
    u64 m = (a < br) ? a : br;
#pragma unroll
    for (int j = 16; j > 0; j >>= 1) {
        const u64 o = __shfl_xor_sync(0xffffffffu, m, j);
        const bool keepMin = ((lane & j) == 0);
        m = ((m < o) == keepMin) ? m : o;
    }
    return m;
}
__device__ __forceinline__ void flush_merge(u64& v, u64& kth,
                                            const u64* buf, int cnt, int lane) {
    __syncwarp();
    u64 b0 = (lane < cnt) ? buf[lane] : ~0ull;
    b0 = sort32(b0, lane);
    if (cnt > 32) {
        u64 b1 = (32 + lane < cnt) ? buf[32 + lane] : ~0ull;
        b1 = sort32(b1, lane);
        b0 = merge_lower(b0, b1, lane);
    }
    v = merge_lower(v, b0, lane);
    kth = __shfl_sync(0xffffffffu, v, 15);
}

#define WPB  16
#define TILE 1024

__global__ void __launch_bounds__(32 * WPB) knn_kernel() {
    __shared__ float4 s_cand[TILE];
    __shared__ u64 s_buf[WPB][64];

    const int lane = threadIdx.x & 31;
    const int w    = threadIdx.x >> 5;
    const int row  = blockIdx.x * WPB + w;
    const float4 p = g_pos4[row];

    u64 v   = ~0ull;
    u64 kth = ~0ull;
    int bufcnt = 0;

    for (int base = 0; base < NPTS; base += TILE) {
        __syncthreads();
        for (int i = threadIdx.x; i < TILE; i += 32 * WPB) s_cand[i] = g_pos4[base + i];
        __syncthreads();
#pragma unroll 4
        for (int i = 0; i < TILE; i += 32) {
            const float4 c = s_cand[i + lane];
            const float dot = fmaf(p.x, c.x, fmaf(p.y, c.y, p.z * c.z));
            const float d2  = fmaf(-2.f, dot, p.w + c.w);
            unsigned u = __float_as_uint(d2);
            u = (u & 0x80000000u) ? ~u : (u | 0x80000000u);
            const u64 key = ((u64)u << 32) | (unsigned)(base + i + lane);
            const bool pred = key < kth;
            const unsigned bal = __ballot_sync(0xffffffffu, pred);
            if (bal) {
                if (pred)
                    s_buf[w][bufcnt + __popc(bal & ((1u << lane) - 1u))] = key;
                bufcnt += __popc(bal);
                if (bufcnt > 32) {
                    flush_merge(v, kth, s_buf[w], bufcnt, lane);
                    bufcnt = 0;
                }
            }
        }
    }
    if (bufcnt) flush_merge(v, kth, s_buf[w], bufcnt, lane);
    if (lane < KNB) g_nbr[row * KNB + lane] = (int)(v & 0xFFFFFFFFull);
}

// ---------------------------------------------------------------------------
// Node projection (R6-exact).
// ---------------------------------------------------------------------------
template <int CIN, int C, bool FIRST>
__global__ void __launch_bounds__(128) proj_kernel(const float* __restrict__ x,
                                                   const float* __restrict__ pos,
                                                   const float* __restrict__ nrm,
                                                   const float* __restrict__ Wa,
                                                   const float* __restrict__ ba) {
    constexpr int TPN = C / 4;
    __shared__ __align__(16) float sW[CIN * C];
    __shared__ __align__(16) float sb[C];
    const int t = threadIdx.x;
    for (int i = t; i < CIN * C; i += 128) sW[i] = Wa[i];
    for (int i = t; i < C; i += 128) sb[i] = ba[i];
    __syncthreads();

    const int n  = blockIdx.x * (128 / TPN) + t / TPN;
    const int c0 = (t % TPN) * 4;
    float4 acc = *reinterpret_cast<const float4*>(&sb[c0]);
#pragma unroll
    for (int k = 0; k < CIN; ++k) {
        float xv;
        if (FIRST) xv = (k < 3) ? pos[n * 3 + k] : nrm[n * 3 + (k - 3)];
        else       xv = x[n * CIN + k];
        const float4 wv = *reinterpret_cast<const float4*>(&sW[k * C + c0]);
        acc.x = fmaf(xv, wv.x, acc.x);
        acc.y = fmaf(xv, wv.y, acc.y);
        acc.z = fmaf(xv, wv.z, acc.z);
        acc.w = fmaf(xv, wv.w, acc.w);
    }
    *reinterpret_cast<float4*>(&g_A[n * C + c0]) = acc;
}

// ---------------------------------------------------------------------------
// Fused edge kernel (R6 structure). R17 phase-3 change: lane fi's channels are
// {fi*4..fi*4+3} and {32+fi*4..}, so each weight LDS.128 covers a CONTIGUOUS
// 128B region (1 wavefront) instead of a 256B strided span (2 wavefronts).
// Same instruction count, same per-(edge,channel) accumulation order over c,
// fmax exactly commutative -> bitwise-identical outputs.
// ---------------------------------------------------------------------------
template <int C, int G, int NPB>
__global__ void __launch_bounds__(2 * C) edge_kernel(
    const float* __restrict__ pos,
    const float* __restrict__ Wa, int cin_node,
    const float* __restrict__ gmm, const float* __restrict__ bta,
    const float* __restrict__ Wb,  const float* __restrict__ bb,
    float* __restrict__ out) {
    constexpr int B  = 2 * C;
    constexpr int HS = 20;
    constexpr int NG = 4;
    extern __shared__ float smem[];
    float* s_Wb   = smem;
    float* s_H    = s_Wb + C * C;
    float* s_Wrel = s_H + NG * C * HS;
    float* s_g    = s_Wrel + 3 * C;
    float* s_b    = s_g + C;
    float* s_bb   = s_b + C;

    const int t = threadIdx.x;
    for (int i = t; i < C * C; i += B) s_Wb[i] = Wb[i];
    for (int i = t; i < 3 * C; i += B) s_Wrel[i] = Wa[cin_node * C + i];
    for (int i = t; i < C; i += B) { s_g[i] = gmm[i]; s_b[i] = bta[i]; s_bb[i] = bb[i]; }
    __syncthreads();

    const int e    = t & 15;
    const int g    = t >> 4;
    const int lane = t & 31;
    const int w    = t >> 5;
    const int et   = lane & 3;
    const int fi   = lane >> 2;
    const int q3   = (C == 128) ? (w >> 1) : w;
    const int base = (C == 128) ? (w & 1) * 64 : 0;
    const int c0a  = base + fi * 4;        // channels c0a..c0a+3 (wA)
    const int c0b  = c0a + 32;             // channels c0b..c0b+3 (wC)

    for (int s0 = 0; s0 < NPB; s0 += NG) {
#pragma unroll
        for (int q = 0; q < NG; ++q) {
            const int i = blockIdx.x * NPB + s0 + q;
            float* Hq = s_H + q * C * HS;
            const int j = g_nbr[i * KNB + e];
            const float rx = pos[j * 3 + 0] - pos[i * 3 + 0];
            const float ry = pos[j * 3 + 1] - pos[i * 3 + 1];
            const float rz = pos[j * 3 + 2] - pos[i * 3 + 2];
            const int c0 = g * 8;
            const float* Ar = g_A + j * C + c0;
            const float4 a0 = *reinterpret_cast<const float4*>(Ar);
            const float4 a1 = *reinterpret_cast<const float4*>(Ar + 4);
            float h[8] = {a0.x, a0.y, a0.z, a0.w, a1.x, a1.y, a1.z, a1.w};
            float sum = 0.f;
#pragma unroll
            for (int cc = 0; cc < 8; ++cc) {
                const int c = c0 + cc;
                h[cc] = h[cc] + rx * s_Wrel[c] + ry * s_Wrel[C + c] + rz * s_Wrel[2 * C + c];
                sum += h[cc];
            }
            const float mean = sum * 0.125f;
            float vs = 0.f;
#pragma unroll
            for (int cc = 0; cc < 8; ++cc) { const float d = h[cc] - mean; vs = fmaf(d, d, vs); }
            const float inv = rsqrtf(fmaf(vs, 0.125f, 1e-5f));
#pragma unroll
            for (int cc = 0; cc < 8; ++cc) {
                const int c = c0 + cc;
                const float vv = fmaf((h[cc] - mean) * inv, s_g[c], s_b[c]);
                Hq[c * HS + e] = fmaxf(vv, 0.f);
            }
        }
        __syncthreads();
        // ---- phase 3: 4 edges x (4 + 4) channels per lane, contiguous W loads ----
        {
            const int i = blockIdx.x * NPB + s0 + q3;
            const float* Hq = s_H + q3 * C * HS;
            u64 acc2[4][4];
#pragma unroll
            for (int a = 0; a < 4; ++a)
#pragma unroll
                for (int fp = 0; fp < 4; ++fp) acc2[a][fp] = 0ull;

#pragma unroll 4
            for (int c = 0; c < C; ++c) {
                const float4 h4 = *reinterpret_cast<const float4*>(&Hq[c * HS + et * 4]);
                const ulonglong2 wA = *reinterpret_cast<const ulonglong2*>(&s_Wb[c * C + c0a]);
                const ulonglong2 wC = *reinterpret_cast<const ulonglong2*>(&s_Wb[c * C + c0b]);
                const u64 wv[4] = {wA.x, wA.y, wC.x, wC.y};
                const u64 hh[4] = {fdup(h4.x), fdup(h4.y), fdup(h4.z), fdup(h4.w)};
#pragma unroll
                for (int a = 0; a < 4; ++a)
#pragma unroll
                    for (int fp = 0; fp < 4; ++fp)
                        fma2(acc2[a][fp], hh[a], wv[fp]);
            }
            float m[8];
#pragma unroll
            for (int fp = 0; fp < 4; ++fp) {
                const float2 v0 = u2f(acc2[0][fp]);
                const float2 v1 = u2f(acc2[1][fp]);
                const float2 v2 = u2f(acc2[2][fp]);
                const float2 v3 = u2f(acc2[3][fp]);
                m[2 * fp]     = fmaxf(fmaxf(v0.x, v1.x), fmaxf(v2.x, v3.x));
                m[2 * fp + 1] = fmaxf(fmaxf(v0.y, v1.y), fmaxf(v2.y, v3.y));
            }
#pragma unroll
            for (int f = 0; f < 8; ++f) {
                m[f] = fmaxf(m[f], __shfl_xor_sync(0xffffffffu, m[f], 1));
                m[f] = fmaxf(m[f], __shfl_xor_sync(0xffffffffu, m[f], 2));
            }
            if (et == 0) {
                float4 r0, r1;
                r0.x = fmaxf(m[0] + s_bb[c0a + 0], 0.f);
                r0.y = fmaxf(m[1] + s_bb[c0a + 1], 0.f);
                r0.z = fmaxf(m[2] + s_bb[c0a + 2], 0.f);
                r0.w = fmaxf(m[3] + s_bb[c0a + 3], 0.f);
                r1.x = fmaxf(m[4] + s_bb[c0b + 0], 0.f);
                r1.y = fmaxf(m[5] + s_bb[c0b + 1], 0.f);
                r1.z = fmaxf(m[6] + s_bb[c0b + 2], 0.f);
                r1.w = fmaxf(m[7] + s_bb[c0b + 3], 0.f);
                *reinterpret_cast<float4*>(&out[i * C + c0a]) = r0;
                *reinterpret_cast<float4*>(&out[i * C + c0b]) = r1;
            }
        }
        __syncthreads();
    }
}

// ---------------------------------------------------------------------------
extern "C" void kernel_launch(void* const* d_in, const int* in_sizes, int n_in,
                              void* d_out, int out_size) {
    const float* pos    = (const float*)d_in[0];
    const float* normal = (const float*)d_in[1];
    const float* W1a = (const float*)d_in[2];
    const float* b1a = (const float*)d_in[3];
    const float* g1  = (const float*)d_in[4];
    const float* be1 = (const float*)d_in[5];
    const float* W1b = (const float*)d_in[6];
    const float* b1b = (const float*)d_in[7];
    const float* W2a = (const float*)d_in[8];
    const float* b2a = (const float*)d_in[9];
    const float* g2  = (const float*)d_in[10];
    const float* be2 = (const float*)d_in[11];
    const float* W2b = (const float*)d_in[12];
    const float* b2b = (const float*)d_in[13];
    const float* W3a = (const float*)d_in[14];
    const float* b3a = (const float*)d_in[15];
    const float* g3  = (const float*)d_in[16];
    const float* be3 = (const float*)d_in[17];
    const float* W3b = (const float*)d_in[18];
    const float* b3b = (const float*)d_in[19];

    float* out = (float*)d_out;
    float* h1 = out;
    float* h2 = out + NPTS * 64;
    float* h3 = out + NPTS * 128;

    const int SMEM64  = (64 * 64  + 4 * 64 * 20  + 3 * 64  + 3 * 64)  * 4;
    const int SMEM128 = (128 * 128 + 4 * 128 * 20 + 3 * 128 + 3 * 128) * 4;
    cudaFuncSetAttribute((const void*)edge_kernel<64, 8, 8>,
                         cudaFuncAttributeMaxDynamicSharedMemorySize, SMEM64);
    cudaFuncSetAttribute((const void*)edge_kernel<128, 16, 8>,
                         cudaFuncAttributeMaxDynamicSharedMemorySize, SMEM128);

    pos4_kernel<<<NPTS / 256, 256>>>(pos);
    knn_kernel<<<NPTS / WPB, 32 * WPB>>>();

    proj_kernel<6, 64, true><<<NPTS / 8, 128>>>(nullptr, pos, normal, W1a, b1a);
    edge_kernel<64, 8, 8><<<NPTS / 8, 128, SMEM64>>>(pos, W1a, 6, g1, be1, W1b, b1b, h1);

    proj_kernel<64, 64, false><<<NPTS / 8, 128>>>(h1, nullptr, nullptr, W2a, b2a);
    edge_kernel<64, 8, 8><<<NPTS / 8, 128, SMEM64>>>(pos, W2a, 64, g2, be2, W2b, b2b, h2);

    proj_kernel<64, 128, false><<<NPTS / 4, 128>>>(h2, nullptr, nullptr, W3a, b3a);
    edge_kernel<128, 16, 8><<<NPTS / 8, 256, SMEM128>>>(pos, W3a, 64, g3, be3, W3b, b3b, h3);
}